// round 8
// baseline (speedup 1.0000x reference)
#include <cuda_runtime.h>
#include <math.h>
#include <stdint.h>

// ---------------- geometry ----------------
#define W_    2048
#define HOUT  2046                 // VALID 3x3 output dim
#define NTOT  (W_ * W_)

// warp-strip decomposition: thread = 2 cols (float2), warp = 64 input cols,
// 62 owned output cols. Strip 32 ends exactly at col 2048 -> no col clipping.
#define COLS_OUT 62
#define R_OUT  20
#define STRIPS 33                  // 33*62 = 2046 exactly
#define BANDS  103                 // ceil(2046/20)
#define NWARPS (STRIPS * BANDS)    // 3399
#define WPB    8                   // warps per block (256 threads)
#define NBLOCKS ((NWARPS + WPB - 1) / WPB)  // 425 -> single wave @ 3 blocks/SM

// per-warp SMEM ring: DEPTH slots, one input row each (64 cols):
//   [0..255]    E    (64 floats)
//   [256..511]  v    (64 floats)
//   [512..1279] strain (192 floats, gmem order)
#define DEPTH 4
#define SLOT_F2 160                // 1280 bytes / 8

__device__ float g_bpart[3 * NBLOCKS];
__device__ unsigned int g_count;   // zero at module load; reset by last block

// ---- cp.async helpers ----
#define CP_ASYNC8(dst, src) \
    asm volatile("cp.async.ca.shared.global [%0], [%1], 8;" :: "r"(dst), "l"(src) : "memory")
#define CP_COMMIT() asm volatile("cp.async.commit_group;" ::: "memory")
#define CP_WAIT(n)  asm volatile("cp.async.wait_group %0;" :: "n"(n) : "memory")

// per-row derived state: horizontal 3-sums and horizontal differences
struct RowState {
    float hE0, hE1;     // 3-sum of E centered at c0 / c0+1
    float hXX0, hXX1;   // 3-sum of sxx
    float hXY0, hXY1;   // 3-sum of sxy
    float dXY0, dXY1;   // sxy(j-1) - sxy(j+1)
    float dYY0, dYY1;   // syy(j-1) - syy(j+1)
};

__device__ __forceinline__ float warp_sum(float x) {
#pragma unroll
    for (int o = 16; o > 0; o >>= 1) x += __shfl_down_sync(0xffffffffu, x, o);
    return x;
}

// issue one row's loads into a ring slot (5 x 8B cp.async per thread)
__device__ __forceinline__ void issue_row(
    uint32_t slot_saddr, int lane,
    const float* __restrict__ pE, const float* __restrict__ pv,
    const float* __restrict__ ps, int r, int c0)
{
    const int rr = (r < W_) ? r : (W_ - 1);      // clamp (last band only)
    const int base = rr * W_ + c0 - 2 * lane;    // row base (c0 includes lane*2)
    const float* srcE = pE + base + 2 * lane;
    const float* srcv = pv + base + 2 * lane;
    const float* srcs = ps + 3 * base + 6 * lane;
    CP_ASYNC8(slot_saddr + lane * 8,             srcE);
    CP_ASYNC8(slot_saddr + 256 + lane * 8,       srcv);
    CP_ASYNC8(slot_saddr + 512 + lane * 24,      srcs);
    CP_ASYNC8(slot_saddr + 512 + lane * 24 + 8,  srcs + 2);
    CP_ASYNC8(slot_saddr + 512 + lane * 24 + 16, srcs + 4);
    CP_COMMIT();
}

__device__ __forceinline__ void compute_row(
    const float2* __restrict__ slot, int lane, RowState& o,
    bool ownrow, bool ownc0, bool ownc1, float& accE)
{
    const float2 E2  = slot[lane];
    const float2 v2  = slot[32 + lane];
    const float2 s01 = slot[64 + lane * 3];
    const float2 s23 = slot[64 + lane * 3 + 1];
    const float2 s45 = slot[64 + lane * 3 + 2];

    const float E0 = E2.x,  E1 = E2.y;
    const float v0 = v2.x,  v1 = v2.y;
    const float e00 = s01.x, e10 = s01.y, e20 = s23.x;  // col c0
    const float e01 = s23.y, e11 = s45.x, e21 = s45.y;  // col c0+1

    const float f0 = __fdividef(E0, 1.0f - v0 * v0);
    const float f1 = __fdividef(E1, 1.0f - v1 * v1);
    const float xx0 = (e00 + v0 * e10) * f0;
    const float xx1 = (e01 + v1 * e11) * f1;
    const float yy0 = (v0 * e00 + e10) * f0;
    const float yy1 = (v1 * e01 + e11) * f1;
    const float xy0 = e20 * (1.0f - v0) * 0.5f * f0;
    const float xy1 = e21 * (1.0f - v1) * 0.5f * f1;

    // 8 shuffles/row; lane-edge garbage only feeds excluded outputs p=0/p=63
    const float El = __shfl_up_sync  (0xffffffffu, E1,  1);
    const float Er = __shfl_down_sync(0xffffffffu, E0,  1);
    const float xl = __shfl_up_sync  (0xffffffffu, xx1, 1);
    const float xr = __shfl_down_sync(0xffffffffu, xx0, 1);
    const float yl = __shfl_up_sync  (0xffffffffu, xy1, 1);
    const float yr = __shfl_down_sync(0xffffffffu, xy0, 1);
    const float sl = __shfl_up_sync  (0xffffffffu, yy1, 1);
    const float sr = __shfl_down_sync(0xffffffffu, yy0, 1);

    o.hE0  = El + E0 + E1;   o.hE1  = E0 + E1 + Er;
    o.hXX0 = xl + xx0 + xx1; o.hXX1 = xx0 + xx1 + xr;
    o.hXY0 = yl + xy0 + xy1; o.hXY1 = xy0 + xy1 + yr;
    o.dXY0 = yl - xy1;       o.dXY1 = xy0 - yr;
    o.dYY0 = sl - yy1;       o.dYY1 = yy0 - sr;

    if (ownrow) {
        if (ownc0) accE += E0;
        if (ownc1) accE += E1;
    }
}

__global__ __launch_bounds__(256, 3)
void stress_loss_kernel(const float* __restrict__ pE,
                        const float* __restrict__ pv,
                        const float* __restrict__ ps,
                        float* __restrict__ out)
{
    __shared__ float2 ring[WPB][DEPTH][SLOT_F2];   // 40960 B

    const int wl   = threadIdx.x >> 5;
    const int w    = blockIdx.x * WPB + wl;
    const int lane = threadIdx.x & 31;
    const int tid  = threadIdx.x;
    float accx = 0.f, accy = 0.f, accE = 0.f;

    if (w < NWARPS) {
        const int strip = w / BANDS;
        const int band  = w - strip * BANDS;
        const int cb = strip * COLS_OUT;
        const int r0 = band * R_OUT;
        const int rows_out = min(R_OUT, HOUT - r0);
        const int c0 = cb + lane * 2;
        const int own_hi_c = (strip == STRIPS - 1) ? W_ : cb + COLS_OUT;
        const int own_hi_r = (band  == BANDS  - 1) ? W_ : r0 + R_OUT;
        const bool ownc0 = (c0     < own_hi_c);
        const bool ownc1 = (c0 + 1 < own_hi_c);
        const bool ok0 = (lane > 0);
        const bool ok1 = (lane < 31);

        uint32_t saddr[DEPTH];
#pragma unroll
        for (int s = 0; s < DEPTH; s++)
            saddr[s] = (uint32_t)__cvta_generic_to_shared(&ring[wl][s][0]);

        // ---- prologue: fill the ring ----
        issue_row(saddr[0], lane, pE, pv, ps, r0,     c0);
        issue_row(saddr[1], lane, pE, pv, ps, r0 + 1, c0);
        issue_row(saddr[2], lane, pE, pv, ps, r0 + 2, c0);
        issue_row(saddr[3], lane, pE, pv, ps, r0 + 3, c0);

        RowState A, B, C;
        CP_WAIT(2);   // rows r0, r0+1 landed
        compute_row(&ring[wl][0][0], lane, A, (r0     < own_hi_r), ownc0, ownc1, accE);
        compute_row(&ring[wl][1][0], lane, B, (r0 + 1 < own_hi_r), ownc0, ownc1, accE);

        for (int i = 0; i < rows_out; i++) {
            // refill the slot consumed two iterations ago, THEN wait: keeps
            // exactly 2 rows in flight at all times, issue decoupled from compute
            issue_row(saddr[i & 3], lane, pE, pv, ps, r0 + i + 4, c0);
            CP_WAIT(2);   // all but newest 2 done -> row r0+i+2 ready

            const int r = r0 + i + 2;
            compute_row(&ring[wl][(i + 2) & 3][0], lane, C,
                        (r < own_hi_r), ownc0, ownc1, accE);

            if (ok0) {
                const float Ec = A.hE0 + B.hE0 + C.hE0;
                const float fx = C.hXX0 - A.hXX0 + (A.dXY0 + B.dXY0 + C.dXY0);
                const float fy = (A.dYY0 + B.dYY0 + C.dYY0) + C.hXY0 - A.hXY0;
                const float inv = __fdividef(1.0f, Ec);
                accx += fabsf(fx * inv);
                accy += fabsf(fy * inv);
            }
            if (ok1) {
                const float Ec = A.hE1 + B.hE1 + C.hE1;
                const float fx = C.hXX1 - A.hXX1 + (A.dXY1 + B.dXY1 + C.dXY1);
                const float fy = (A.dYY1 + B.dYY1 + C.dYY1) + C.hXY1 - A.hXY1;
                const float inv = __fdividef(1.0f, Ec);
                accx += fabsf(fx * inv);
                accy += fabsf(fy * inv);
            }
            A = B; B = C;
        }
        CP_WAIT(0);   // drain before slots could be reused by reduction phase
    }

    // ---- block reduction ----
    accx = warp_sum(accx);
    accy = warp_sum(accy);
    accE = warp_sum(accE);

    __shared__ float red[3][WPB];
    __shared__ int isLast;
    if (lane == 0) {
        red[0][wl] = accx;
        red[1][wl] = accy;
        red[2][wl] = accE;
    }
    __syncthreads();
    if (tid == 0) {
        float ax = 0.f, ay = 0.f, ae = 0.f;
#pragma unroll
        for (int q = 0; q < WPB; q++) { ax += red[0][q]; ay += red[1][q]; ae += red[2][q]; }
        g_bpart[blockIdx.x]               = ax;
        g_bpart[NBLOCKS + blockIdx.x]     = ay;
        g_bpart[2 * NBLOCKS + blockIdx.x] = ae;
        __threadfence();
        const unsigned int old = atomicAdd(&g_count, 1u);
        isLast = (old == NBLOCKS - 1);
    }
    __syncthreads();

    // ---- last block finalizes (fixed-order sum -> deterministic) ----
    if (isLast) {
        volatile const float* vp = (volatile const float*)g_bpart;
        double ax = 0.0, ay = 0.0, ae = 0.0;
        for (int i = tid; i < NBLOCKS; i += 256) {
            ax += (double)vp[i];
            ay += (double)vp[NBLOCKS + i];
            ae += (double)vp[2 * NBLOCKS + i];
        }
        __shared__ double sax[256], say[256], sae[256];
        sax[tid] = ax; say[tid] = ay; sae[tid] = ae;
        __syncthreads();
        for (int s = 128; s > 0; s >>= 1) {
            if (tid < s) { sax[tid] += sax[tid + s]; say[tid] += say[tid + s]; sae[tid] += sae[tid + s]; }
            __syncthreads();
        }
        if (tid == 0) {
            const double M = (double)HOUT * (double)HOUT;
            out[0] = (float)(sax[0] / M + say[0] / M
                             + fabs(sae[0] / (double)NTOT - 1.0) / 100.0);
            g_count = 0;   // reset for next graph replay
        }
    }
}

extern "C" void kernel_launch(void* const* d_in, const int* in_sizes, int n_in,
                              void* d_out, int out_size)
{
    const float* pred_E = (const float*)d_in[0];
    const float* pred_v = (const float*)d_in[1];
    const float* strain = (const float*)d_in[2];
    float* out = (float*)d_out;

    stress_loss_kernel<<<NBLOCKS, 256>>>(pred_E, pred_v, strain, out);
}

// round 9
// speedup vs baseline: 1.0783x; 1.0783x over previous
#include <cuda_runtime.h>
#include <math.h>
#include <stdint.h>

// ---------------- geometry ----------------
#define W_    2048
#define HOUT  2046                 // VALID 3x3 output dim
#define NTOT  (W_ * W_)

// warp-strip decomposition: thread = 2 cols (float2), warp = 64 input cols,
// 62 owned output cols. Deep cp.async ring: 8 slots, ~5 rows in flight.
#define COLS_OUT 62
#define R_OUT  30
#define STRIPS 33                  // 33*62 = 2046 exactly
#define BANDS  69                  // ceil(2046/30)
#define NWARPS (STRIPS * BANDS)    // 2277
#define WPB    8                   // warps per block (256 threads)
#define NBLOCKS ((NWARPS + WPB - 1) / WPB)  // 285 -> balanced single wave @2/SM

// per-warp SMEM ring: DEPTH slots, one input row each (64 cols):
//   [0..255]    E    (64 floats)
//   [256..511]  v    (64 floats)
//   [512..1279] strain (192 floats, gmem order)
#define DEPTH 8
#define SLOT_BYTES 1280
#define RING_BYTES (WPB * DEPTH * SLOT_BYTES)   // 81920

__device__ float g_bpart[3 * NBLOCKS];
__device__ unsigned int g_count;   // zero at module load; reset by last block

// ---- cp.async helpers ----
#define CP_ASYNC8(dst, src) \
    asm volatile("cp.async.ca.shared.global [%0], [%1], 8;" :: "r"(dst), "l"(src) : "memory")
#define CP_COMMIT() asm volatile("cp.async.commit_group;" ::: "memory")
#define CP_WAIT(n)  asm volatile("cp.async.wait_group %0;" :: "n"(n) : "memory")

// per-row derived state: horizontal 3-sums and horizontal differences
struct RowState {
    float hE0, hE1;     // 3-sum of E centered at c0 / c0+1
    float hXX0, hXX1;   // 3-sum of sxx
    float hXY0, hXY1;   // 3-sum of sxy
    float dXY0, dXY1;   // sxy(j-1) - sxy(j+1)
    float dYY0, dYY1;   // syy(j-1) - syy(j+1)
};

__device__ __forceinline__ float warp_sum(float x) {
#pragma unroll
    for (int o = 16; o > 0; o >>= 1) x += __shfl_down_sync(0xffffffffu, x, o);
    return x;
}

// issue one row's loads into a ring slot (5 x 8B cp.async per thread)
__device__ __forceinline__ void issue_row(
    uint32_t slot_saddr, int lane,
    const float* __restrict__ pE, const float* __restrict__ pv,
    const float* __restrict__ ps, int r, int c0)
{
    const int rr = (r < W_) ? r : (W_ - 1);      // clamp (last band only)
    const int base = rr * W_ + c0;
    const float* srcE = pE + base;
    const float* srcv = pv + base;
    const float* srcs = ps + 3 * (base - 2 * lane) + 6 * lane;
    CP_ASYNC8(slot_saddr + lane * 8,             srcE);
    CP_ASYNC8(slot_saddr + 256 + lane * 8,       srcv);
    CP_ASYNC8(slot_saddr + 512 + lane * 24,      srcs);
    CP_ASYNC8(slot_saddr + 512 + lane * 24 + 8,  srcs + 2);
    CP_ASYNC8(slot_saddr + 512 + lane * 24 + 16, srcs + 4);
    CP_COMMIT();
}

__device__ __forceinline__ void compute_row(
    const float2* __restrict__ slot, int lane, RowState& o,
    bool ownrow, bool ownc0, bool ownc1, float& accE)
{
    const float2 E2  = slot[lane];
    const float2 v2  = slot[32 + lane];
    const float2 s01 = slot[64 + lane * 3];
    const float2 s23 = slot[64 + lane * 3 + 1];
    const float2 s45 = slot[64 + lane * 3 + 2];

    const float E0 = E2.x,  E1 = E2.y;
    const float v0 = v2.x,  v1 = v2.y;
    const float e00 = s01.x, e10 = s01.y, e20 = s23.x;  // col c0
    const float e01 = s23.y, e11 = s45.x, e21 = s45.y;  // col c0+1

    const float f0 = __fdividef(E0, 1.0f - v0 * v0);
    const float f1 = __fdividef(E1, 1.0f - v1 * v1);
    const float xx0 = (e00 + v0 * e10) * f0;
    const float xx1 = (e01 + v1 * e11) * f1;
    const float yy0 = (v0 * e00 + e10) * f0;
    const float yy1 = (v1 * e01 + e11) * f1;
    const float xy0 = e20 * (1.0f - v0) * 0.5f * f0;
    const float xy1 = e21 * (1.0f - v1) * 0.5f * f1;

    // 8 shuffles/row; lane-edge garbage only feeds excluded outputs p=0/p=63
    const float El = __shfl_up_sync  (0xffffffffu, E1,  1);
    const float Er = __shfl_down_sync(0xffffffffu, E0,  1);
    const float xl = __shfl_up_sync  (0xffffffffu, xx1, 1);
    const float xr = __shfl_down_sync(0xffffffffu, xx0, 1);
    const float yl = __shfl_up_sync  (0xffffffffu, xy1, 1);
    const float yr = __shfl_down_sync(0xffffffffu, xy0, 1);
    const float sl = __shfl_up_sync  (0xffffffffu, yy1, 1);
    const float sr = __shfl_down_sync(0xffffffffu, yy0, 1);

    o.hE0  = El + E0 + E1;   o.hE1  = E0 + E1 + Er;
    o.hXX0 = xl + xx0 + xx1; o.hXX1 = xx0 + xx1 + xr;
    o.hXY0 = yl + xy0 + xy1; o.hXY1 = xy0 + xy1 + yr;
    o.dXY0 = yl - xy1;       o.dXY1 = xy0 - yr;
    o.dYY0 = sl - yy1;       o.dYY1 = yy0 - sr;

    if (ownrow) {
        if (ownc0) accE += E0;
        if (ownc1) accE += E1;
    }
}

__global__ __launch_bounds__(256, 2)
void stress_loss_kernel(const float* __restrict__ pE,
                        const float* __restrict__ pv,
                        const float* __restrict__ ps,
                        float* __restrict__ out)
{
    extern __shared__ char ring_raw[];             // RING_BYTES dynamic

    const int wl   = threadIdx.x >> 5;
    const int w    = blockIdx.x * WPB + wl;
    const int lane = threadIdx.x & 31;
    const int tid  = threadIdx.x;
    float accx = 0.f, accy = 0.f, accE = 0.f;

    if (w < NWARPS) {
        const int strip = w / BANDS;
        const int band  = w - strip * BANDS;
        const int cb = strip * COLS_OUT;
        const int r0 = band * R_OUT;
        const int rows_out = min(R_OUT, HOUT - r0);
        const int c0 = cb + lane * 2;
        const int own_hi_c = (strip == STRIPS - 1) ? W_ : cb + COLS_OUT;
        const int own_hi_r = (band  == BANDS  - 1) ? W_ : r0 + R_OUT;
        const bool ownc0 = (c0     < own_hi_c);
        const bool ownc1 = (c0 + 1 < own_hi_c);
        const bool ok0 = (lane > 0);
        const bool ok1 = (lane < 31);

        char* warp_ring = ring_raw + wl * (DEPTH * SLOT_BYTES);
        const uint32_t sbase =
            (uint32_t)__cvta_generic_to_shared(warp_ring);

        // ---- prologue: issue 6 rows (6 groups in flight) ----
#pragma unroll
        for (int s = 0; s < 6; s++)
            issue_row(sbase + s * SLOT_BYTES, lane, pE, pv, ps, r0 + s, c0);

        RowState A, B, C;
        CP_WAIT(4);   // rows r0, r0+1 landed
        compute_row((const float2*)(warp_ring + 0 * SLOT_BYTES), lane, A,
                    (r0     < own_hi_r), ownc0, ownc1, accE);
        compute_row((const float2*)(warp_ring + 1 * SLOT_BYTES), lane, B,
                    (r0 + 1 < own_hi_r), ownc0, ownc1, accE);

        for (int i = 0; i < rows_out; i++) {
            // issue row r0+i+6 into slot (i+6)&7 (reuses slot consumed at i-2)
            issue_row(sbase + ((i + 6) & 7) * SLOT_BYTES, lane,
                      pE, pv, ps, r0 + i + 6, c0);
            CP_WAIT(4);   // all but newest 4 landed -> row r0+i+2 ready

            const int r = r0 + i + 2;
            compute_row((const float2*)(warp_ring + ((i + 2) & 7) * SLOT_BYTES),
                        lane, C, (r < own_hi_r), ownc0, ownc1, accE);

            if (ok0) {
                const float Ec = A.hE0 + B.hE0 + C.hE0;
                const float fx = C.hXX0 - A.hXX0 + (A.dXY0 + B.dXY0 + C.dXY0);
                const float fy = (A.dYY0 + B.dYY0 + C.dYY0) + C.hXY0 - A.hXY0;
                const float inv = __fdividef(1.0f, Ec);
                accx += fabsf(fx * inv);
                accy += fabsf(fy * inv);
            }
            if (ok1) {
                const float Ec = A.hE1 + B.hE1 + C.hE1;
                const float fx = C.hXX1 - A.hXX1 + (A.dXY1 + B.dXY1 + C.dXY1);
                const float fy = (A.dYY1 + B.dYY1 + C.dYY1) + C.hXY1 - A.hXY1;
                const float inv = __fdividef(1.0f, Ec);
                accx += fabsf(fx * inv);
                accy += fabsf(fy * inv);
            }
            A = B; B = C;
        }
        CP_WAIT(0);   // drain outstanding groups
    }

    // ---- block reduction ----
    accx = warp_sum(accx);
    accy = warp_sum(accy);
    accE = warp_sum(accE);

    __shared__ float red[3][WPB];
    __shared__ int isLast;
    if (lane == 0) {
        red[0][wl] = accx;
        red[1][wl] = accy;
        red[2][wl] = accE;
    }
    __syncthreads();
    if (tid == 0) {
        float ax = 0.f, ay = 0.f, ae = 0.f;
#pragma unroll
        for (int q = 0; q < WPB; q++) { ax += red[0][q]; ay += red[1][q]; ae += red[2][q]; }
        g_bpart[blockIdx.x]               = ax;
        g_bpart[NBLOCKS + blockIdx.x]     = ay;
        g_bpart[2 * NBLOCKS + blockIdx.x] = ae;
        __threadfence();
        const unsigned int old = atomicAdd(&g_count, 1u);
        isLast = (old == NBLOCKS - 1);
    }
    __syncthreads();

    // ---- last block finalizes (fixed-order sum -> deterministic) ----
    if (isLast) {
        volatile const float* vp = (volatile const float*)g_bpart;
        double ax = 0.0, ay = 0.0, ae = 0.0;
        for (int i = tid; i < NBLOCKS; i += 256) {
            ax += (double)vp[i];
            ay += (double)vp[NBLOCKS + i];
            ae += (double)vp[2 * NBLOCKS + i];
        }
        __shared__ double sax[256], say[256], sae[256];
        sax[tid] = ax; say[tid] = ay; sae[tid] = ae;
        __syncthreads();
        for (int s = 128; s > 0; s >>= 1) {
            if (tid < s) { sax[tid] += sax[tid + s]; say[tid] += say[tid + s]; sae[tid] += sae[tid + s]; }
            __syncthreads();
        }
        if (tid == 0) {
            const double M = (double)HOUT * (double)HOUT;
            out[0] = (float)(sax[0] / M + say[0] / M
                             + fabs(sae[0] / (double)NTOT - 1.0) / 100.0);
            g_count = 0;   // reset for next graph replay
        }
    }
}

extern "C" void kernel_launch(void* const* d_in, const int* in_sizes, int n_in,
                              void* d_out, int out_size)
{
    const float* pred_E = (const float*)d_in[0];
    const float* pred_v = (const float*)d_in[1];
    const float* strain = (const float*)d_in[2];
    float* out = (float*)d_out;

    static int configured = 0;
    if (!configured) {
        cudaFuncSetAttribute(stress_loss_kernel,
                             cudaFuncAttributeMaxDynamicSharedMemorySize,
                             RING_BYTES);
        configured = 1;
    }

    stress_loss_kernel<<<NBLOCKS, 256, RING_BYTES>>>(pred_E, pred_v, strain, out);
}